// round 9
// baseline (speedup 1.0000x reference)
#include <cuda_runtime.h>

#define BB 4
#define LL 5
#define CC 256
#define HW 25200
#define KSEL 1024
#define NSLICE (BB*LL)
#define HW4 (HW/4)
#define UN 4          // float4s per thread in apply
#define APPLY_T 256
#define CAND_MAX 1024

// scratch (no allocations allowed)
__device__ unsigned g_keys[NSLICE * HW];      // order-preserving keys
__device__ unsigned g_fmask[NSLICE * HW4];    // 4 bytes per uint, 1 byte per hw

__device__ __forceinline__ unsigned f2ord(float f) {
    unsigned u = __float_as_uint(f);
    return u ^ ((unsigned)((int)u >> 31) | 0x80000000u);  // monotone float->uint
}

// K1 (wide): keys[slice][hw] = ord(max_c(psm[b,l,c,hw] - psm[b,0,c,hw])).
// One uint4 (4 hw) per thread; psm read with float4.
__global__ void compute_keys_kernel(const float* __restrict__ psm) {
    int i = blockIdx.x * blockDim.x + threadIdx.x;
    if (i >= NSLICE * HW4) return;
    const int slice = i / HW4;
    const int j = i - slice * HW4;
    const int b = slice / LL;

    const float4* __restrict__ pl = (const float4*)(psm + (size_t)slice * 2 * HW);
    const float4* __restrict__ p0 = (const float4*)(psm + (size_t)(b * LL) * 2 * HW);
    float4 a0 = pl[j], a1 = pl[j + HW4];
    float4 e0 = p0[j], e1 = p0[j + HW4];
    uint4 k;
    k.x = f2ord(fmaxf(a0.x - e0.x, a1.x - e1.x));
    k.y = f2ord(fmaxf(a0.y - e0.y, a1.y - e1.y));
    k.z = f2ord(fmaxf(a0.z - e0.z, a1.z - e1.z));
    k.w = f2ord(fmaxf(a0.w - e0.w, a1.w - e1.w));
    ((uint4*)g_keys)[i] = k;
}

// K2 (20 blocks): all data L2-resident. Histogram top-11 bits, shfl suffix
// scan, gather candidates of threshold bin, resolve low 21 bits via
// syncthreads_count, write byte mask. Fallback radix passes if degenerate.
__global__ void select_finish_kernel() {
    __shared__ unsigned hist[2048];
    __shared__ unsigned aux[2048];
    __shared__ unsigned cand[CAND_MAX];
    __shared__ unsigned warpsum[32];
    __shared__ unsigned s_sel, s_cnt, s_thresh;
    __shared__ int s_k, s_cand_n;

    const int slice = blockIdx.x;
    const unsigned* __restrict__ keys = g_keys + (size_t)slice * HW;
    const int tid = threadIdx.x;
    const int nt = blockDim.x;        // 1024
    const int lane = tid & 31;
    const int wid = tid >> 5;

    // ---- histogram of top 11 bits (keys are L2 hits) ----
    hist[tid] = 0u; hist[tid + 1024] = 0u;
    __syncthreads();
    {
        const uint4* k4 = (const uint4*)keys;
        for (int j = tid; j < HW4; j += nt) {
            uint4 kk = __ldg(k4 + j);
            atomicAdd(&hist[kk.x >> 21], 1u);
            atomicAdd(&hist[kk.y >> 21], 1u);
            atomicAdd(&hist[kk.z >> 21], 1u);
            atomicAdd(&hist[kk.w >> 21], 1u);
        }
    }
    __syncthreads();

    // ---- block suffix scan over 2048 bins (shfl-based) ----
    {
        unsigned ps = hist[2 * tid];
        unsigned s  = ps + hist[2 * tid + 1];
        unsigned v = s;
        #pragma unroll
        for (int d = 1; d < 32; d <<= 1) {
            unsigned t = __shfl_down_sync(0xffffffffu, v, d);
            if (lane + d < 32) v += t;
        }
        if (lane == 0) warpsum[wid] = v;
        __syncthreads();
        if (wid == 0) {
            unsigned wv = warpsum[lane];
            unsigned sv = wv;
            #pragma unroll
            for (int d = 1; d < 32; d <<= 1) {
                unsigned t = __shfl_down_sync(0xffffffffu, sv, d);
                if (lane + d < 32) sv += t;
            }
            warpsum[lane] = sv - wv;   // exclusive suffix of warp totals
        }
        __syncthreads();
        unsigned P = v + warpsum[wid];
        aux[2 * tid]     = P;
        aux[2 * tid + 1] = P - ps;
    }
    __syncthreads();

    // ---- locate threshold bin: S[j] >= K > S[j+1] ----
    #pragma unroll
    for (int q = 0; q < 2; ++q) {
        int j = 2 * tid + q;
        unsigned sj  = aux[j];
        unsigned sj1 = (j < 2047) ? aux[j + 1] : 0u;
        if (sj >= KSEL && sj1 < KSEL) {
            s_sel = (unsigned)j;
            s_k   = KSEL - (int)sj1;
            s_cnt = sj - sj1;
        }
    }
    __syncthreads();

    const unsigned sel = s_sel;
    if (s_cnt <= CAND_MAX) {
        if (tid == 0) s_cand_n = 0;
        __syncthreads();
        for (int j = tid; j < HW; j += nt) {
            unsigned u = __ldg(keys + j);
            if ((u >> 21) == sel) {
                int p = atomicAdd(&s_cand_n, 1);
                cand[p] = u;
            }
        }
        __syncthreads();
        const int cn = s_cand_n;
        unsigned c = (tid < cn) ? cand[tid] : 0u;
        bool alive = (tid < cn);
        int k = s_k;
        unsigned low = 0u;
        for (int bit = 20; bit >= 0; --bit) {
            int n1 = __syncthreads_count(alive && ((c >> bit) & 1u));
            if (n1 >= k) { alive = alive && ((c >> bit) & 1u); low |= (1u << bit); }
            else         { k -= n1; alive = alive && !((c >> bit) & 1u); }
        }
        if (tid == 0) s_thresh = (sel << 21) | low;
        __syncthreads();
    } else {
        // fallback: radix passes on bits [10:21) then [0:10)
        unsigned prefix = sel << 21;
        unsigned decided = 0x7FFu << 21;
        int kk = s_k;
        const int shifts[2]  = {10, 0};
        const int nbitsA[2]  = {11, 10};
        #pragma unroll
        for (int p = 0; p < 2; ++p) {
            const int shift = shifts[p];
            const int nb = 1 << nbitsA[p];
            const unsigned bm = (unsigned)nb - 1u;
            for (int j = tid; j < nb; j += nt) hist[j] = 0u;
            __syncthreads();
            for (int j = tid; j < HW; j += nt) {
                unsigned u = __ldg(keys + j);
                if ((u & decided) == prefix)
                    atomicAdd(&hist[(u >> shift) & bm], 1u);
            }
            __syncthreads();
            unsigned* src = hist;
            unsigned* dst = aux;
            for (int d = 1; d < nb; d <<= 1) {
                for (int j = tid; j < nb; j += nt)
                    dst[j] = src[j] + ((j + d < nb) ? src[j + d] : 0u);
                __syncthreads();
                unsigned* t = src; src = dst; dst = t;
            }
            for (int j = tid; j < nb; j += nt) {
                int sj  = (int)src[j];
                int sj1 = (j + 1 < nb) ? (int)src[j + 1] : 0;
                if (sj >= kk && sj1 < kk) {
                    s_sel = (unsigned)j;
                    s_cand_n = kk - sj1;
                }
            }
            __syncthreads();
            prefix |= (s_sel << shift);
            kk = s_cand_n;
            decided |= bm << shift;
            __syncthreads();
        }
        if (tid == 0) s_thresh = prefix;
        __syncthreads();
    }

    // ---- write byte mask (keys L2-hit reads) ----
    const unsigned thresh = s_thresh;
    unsigned* fm = g_fmask + slice * HW4;
    const uint4* k4 = (const uint4*)keys;
    for (int j4 = tid; j4 < HW4; j4 += nt) {
        uint4 kk = __ldg(k4 + j4);
        unsigned b0 = (kk.x >= thresh) ? 1u : 0u;
        unsigned b1 = (kk.y >= thresh) ? 1u : 0u;
        unsigned b2 = (kk.z >= thresh) ? 1u : 0u;
        unsigned b3 = (kk.w >= thresh) ? 1u : 0u;
        fm[j4] = b0 | (b1 << 8) | (b2 << 16) | (b3 << 24);
    }
}

// Easy slices: l==0 -> copy x, (l>0 && mask==0) -> zeros. No fmask dependency.
__global__ void apply_easy_kernel(const float* __restrict__ x,
                                  const int* __restrict__ mask,
                                  float* __restrict__ out) {
    const int slice = blockIdx.z;
    const int l = slice % LL;
    const bool is_ego = (l == 0);
    if (!is_ego && mask[slice] != 0) return;   // masked path handled elsewhere

    const int c = blockIdx.y;
    const size_t base = ((size_t)slice * CC + c) * (size_t)HW4;
    const float4* __restrict__ xv = (const float4*)x + base;
    float4* __restrict__ ov = (float4*)out + base;
    const int j0 = blockIdx.x * (APPLY_T * UN) + threadIdx.x;

    if (is_ego) {
        #pragma unroll
        for (int u = 0; u < UN; ++u) {
            int j = j0 + u * APPLY_T;
            if (j < HW4) __stcs(ov + j, __ldcs(xv + j));
        }
    } else {
        const float4 z = make_float4(0.f, 0.f, 0.f, 0.f);
        #pragma unroll
        for (int u = 0; u < UN; ++u) {
            int j = j0 + u * APPLY_T;
            if (j < HW4) __stcs(ov + j, z);
        }
    }
}

// Masked slices: l>0 && mask!=0 -> x * fmask, sparse x reads.
__global__ void apply_masked_kernel(const float* __restrict__ x,
                                    const int* __restrict__ mask,
                                    float* __restrict__ out) {
    const int slice = blockIdx.z;
    const int l = slice % LL;
    if (l == 0 || mask[slice] == 0) return;    // handled by easy kernel

    const int c = blockIdx.y;
    const size_t base = ((size_t)slice * CC + c) * (size_t)HW4;
    const float4* __restrict__ xv = (const float4*)x + base;
    float4* __restrict__ ov = (float4*)out + base;
    const int j0 = blockIdx.x * (APPLY_T * UN) + threadIdx.x;

    const unsigned* __restrict__ fm = g_fmask + slice * HW4;
    unsigned m4[UN];
    #pragma unroll
    for (int u = 0; u < UN; ++u) {
        int j = j0 + u * APPLY_T;
        m4[u] = (j < HW4) ? __ldg(fm + j) : 0u;
    }
    float4 v[UN];
    #pragma unroll
    for (int u = 0; u < UN; ++u) {
        int j = j0 + u * APPLY_T;
        if (j < HW4 && m4[u] != 0u) v[u] = __ldcs(xv + j);
    }
    #pragma unroll
    for (int u = 0; u < UN; ++u) {
        int j = j0 + u * APPLY_T;
        if (j >= HW4) continue;
        float4 w = make_float4(0.f, 0.f, 0.f, 0.f);
        unsigned m = m4[u];
        if (m != 0u) {
            if (m & 0x000000FFu) w.x = v[u].x;
            if (m & 0x0000FF00u) w.y = v[u].y;
            if (m & 0x00FF0000u) w.z = v[u].z;
            if (m & 0xFF000000u) w.w = v[u].w;
        }
        __stcs(ov + j, w);
    }
}

extern "C" void kernel_launch(void* const* d_in, const int* in_sizes, int n_in,
                              void* d_out, int out_size) {
    const float* x = nullptr;
    const float* psm = nullptr;
    const int* mask = nullptr;
    for (int i = 0; i < n_in; ++i) {
        if (in_sizes[i] == BB * LL * CC * HW)      x    = (const float*)d_in[i];
        else if (in_sizes[i] == BB * LL * 2 * HW)  psm  = (const float*)d_in[i];
        else if (in_sizes[i] == BB * LL)           mask = (const int*)d_in[i];
    }
    float* out = (float*)d_out;

    // Lazy host-side resources (no device memory involved).
    static cudaStream_t s_side = nullptr;
    static cudaEvent_t s_fork = nullptr, s_join = nullptr;
    if (!s_side) {
        cudaStreamCreateWithFlags(&s_side, cudaStreamNonBlocking);
        cudaEventCreateWithFlags(&s_fork, cudaEventDisableTiming);
        cudaEventCreateWithFlags(&s_join, cudaEventDisableTiming);
    }

    const int gx = (HW4 + APPLY_T * UN - 1) / (APPLY_T * UN);  // 7
    const dim3 agrid(gx, CC, NSLICE);
    const int kb = (NSLICE * HW4 + 255) / 256;                 // 493

    // Side stream: keys (wide) -> select finish (L2) -> masked-apply.
    // Main stream: easy-apply runs concurrently with all of it.
    cudaEventRecord(s_fork, 0);
    cudaStreamWaitEvent(s_side, s_fork, 0);
    compute_keys_kernel<<<kb, 256, 0, s_side>>>(psm);
    select_finish_kernel<<<NSLICE, 1024, 0, s_side>>>();
    apply_masked_kernel<<<agrid, APPLY_T, 0, s_side>>>(x, mask, out);
    cudaEventRecord(s_join, s_side);

    apply_easy_kernel<<<agrid, APPLY_T>>>(x, mask, out);

    cudaStreamWaitEvent(0, s_join, 0);
}

// round 14
// speedup vs baseline: 1.0316x; 1.0316x over previous
#include <cuda_runtime.h>

#define BB 4
#define LL 5
#define CC 256
#define HW 25200
#define KSEL 1024
#define NSLICE (BB*LL)
#define HW4 (HW/4)
#define UN 4          // float4s per thread in apply
#define APPLY_T 256
#define CAND_MAX 1024

// scratch (no allocations allowed)
__device__ unsigned g_keys[NSLICE * HW];      // order-preserving keys
__device__ unsigned g_fmask[NSLICE * HW4];    // 4 bytes per uint, 1 byte per hw

__device__ __forceinline__ unsigned f2ord(float f) {
    unsigned u = __float_as_uint(f);
    return u ^ ((unsigned)((int)u >> 31) | 0x80000000u);  // monotone float->uint
}

// K1 (wide): keys[slice][hw] = ord(max_c(psm[b,l,c,hw] - psm[b,0,c,hw])).
__global__ void compute_keys_kernel(const float* __restrict__ psm) {
    int i = blockIdx.x * blockDim.x + threadIdx.x;
    if (i >= NSLICE * HW4) return;
    const int slice = i / HW4;
    const int j = i - slice * HW4;
    const int b = slice / LL;

    const float4* __restrict__ pl = (const float4*)(psm + (size_t)slice * 2 * HW);
    const float4* __restrict__ p0 = (const float4*)(psm + (size_t)(b * LL) * 2 * HW);
    float4 a0 = pl[j], a1 = pl[j + HW4];
    float4 e0 = p0[j], e1 = p0[j + HW4];
    uint4 k;
    k.x = f2ord(fmaxf(a0.x - e0.x, a1.x - e1.x));
    k.y = f2ord(fmaxf(a0.y - e0.y, a1.y - e1.y));
    k.z = f2ord(fmaxf(a0.z - e0.z, a1.z - e1.z));
    k.w = f2ord(fmaxf(a0.w - e0.w, a1.w - e1.w));
    ((uint4*)g_keys)[i] = k;
}

// K2 (20 blocks, keys L2-resident): histogram top-11 bits, shfl suffix scan,
// gather candidates of threshold bin, resolve low 21 bits via
// syncthreads_count, write byte mask. Fallback radix passes if degenerate.
__global__ void select_finish_kernel() {
    __shared__ unsigned hist[2048];
    __shared__ unsigned aux[2048];
    __shared__ unsigned cand[CAND_MAX];
    __shared__ unsigned warpsum[32];
    __shared__ unsigned s_sel, s_cnt, s_thresh;
    __shared__ int s_k, s_cand_n;

    const int slice = blockIdx.x;
    const unsigned* __restrict__ keys = g_keys + (size_t)slice * HW;
    const int tid = threadIdx.x;
    const int nt = blockDim.x;        // 1024
    const int lane = tid & 31;
    const int wid = tid >> 5;

    hist[tid] = 0u; hist[tid + 1024] = 0u;
    __syncthreads();
    {
        const uint4* k4 = (const uint4*)keys;
        for (int j = tid; j < HW4; j += nt) {
            uint4 kk = __ldg(k4 + j);
            atomicAdd(&hist[kk.x >> 21], 1u);
            atomicAdd(&hist[kk.y >> 21], 1u);
            atomicAdd(&hist[kk.z >> 21], 1u);
            atomicAdd(&hist[kk.w >> 21], 1u);
        }
    }
    __syncthreads();

    // block suffix scan over 2048 bins
    {
        unsigned ps = hist[2 * tid];
        unsigned s  = ps + hist[2 * tid + 1];
        unsigned v = s;
        #pragma unroll
        for (int d = 1; d < 32; d <<= 1) {
            unsigned t = __shfl_down_sync(0xffffffffu, v, d);
            if (lane + d < 32) v += t;
        }
        if (lane == 0) warpsum[wid] = v;
        __syncthreads();
        if (wid == 0) {
            unsigned wv = warpsum[lane];
            unsigned sv = wv;
            #pragma unroll
            for (int d = 1; d < 32; d <<= 1) {
                unsigned t = __shfl_down_sync(0xffffffffu, sv, d);
                if (lane + d < 32) sv += t;
            }
            warpsum[lane] = sv - wv;
        }
        __syncthreads();
        unsigned P = v + warpsum[wid];
        aux[2 * tid]     = P;
        aux[2 * tid + 1] = P - ps;
    }
    __syncthreads();

    #pragma unroll
    for (int q = 0; q < 2; ++q) {
        int j = 2 * tid + q;
        unsigned sj  = aux[j];
        unsigned sj1 = (j < 2047) ? aux[j + 1] : 0u;
        if (sj >= KSEL && sj1 < KSEL) {
            s_sel = (unsigned)j;
            s_k   = KSEL - (int)sj1;
            s_cnt = sj - sj1;
        }
    }
    __syncthreads();

    const unsigned sel = s_sel;
    if (s_cnt <= CAND_MAX) {
        if (tid == 0) s_cand_n = 0;
        __syncthreads();
        for (int j = tid; j < HW; j += nt) {
            unsigned u = __ldg(keys + j);
            if ((u >> 21) == sel) {
                int p = atomicAdd(&s_cand_n, 1);
                cand[p] = u;
            }
        }
        __syncthreads();
        const int cn = s_cand_n;
        unsigned c = (tid < cn) ? cand[tid] : 0u;
        bool alive = (tid < cn);
        int k = s_k;
        unsigned low = 0u;
        for (int bit = 20; bit >= 0; --bit) {
            int n1 = __syncthreads_count(alive && ((c >> bit) & 1u));
            if (n1 >= k) { alive = alive && ((c >> bit) & 1u); low |= (1u << bit); }
            else         { k -= n1; alive = alive && !((c >> bit) & 1u); }
        }
        if (tid == 0) s_thresh = (sel << 21) | low;
        __syncthreads();
    } else {
        unsigned prefix = sel << 21;
        unsigned decided = 0x7FFu << 21;
        int kk = s_k;
        const int shifts[2]  = {10, 0};
        const int nbitsA[2]  = {11, 10};
        #pragma unroll
        for (int p = 0; p < 2; ++p) {
            const int shift = shifts[p];
            const int nb = 1 << nbitsA[p];
            const unsigned bm = (unsigned)nb - 1u;
            for (int j = tid; j < nb; j += nt) hist[j] = 0u;
            __syncthreads();
            for (int j = tid; j < HW; j += nt) {
                unsigned u = __ldg(keys + j);
                if ((u & decided) == prefix)
                    atomicAdd(&hist[(u >> shift) & bm], 1u);
            }
            __syncthreads();
            unsigned* src = hist;
            unsigned* dst = aux;
            for (int d = 1; d < nb; d <<= 1) {
                for (int j = tid; j < nb; j += nt)
                    dst[j] = src[j] + ((j + d < nb) ? src[j + d] : 0u);
                __syncthreads();
                unsigned* t = src; src = dst; dst = t;
            }
            for (int j = tid; j < nb; j += nt) {
                int sj  = (int)src[j];
                int sj1 = (j + 1 < nb) ? (int)src[j + 1] : 0;
                if (sj >= kk && sj1 < kk) {
                    s_sel = (unsigned)j;
                    s_cand_n = kk - sj1;
                }
            }
            __syncthreads();
            prefix |= (s_sel << shift);
            kk = s_cand_n;
            decided |= bm << shift;
            __syncthreads();
        }
        if (tid == 0) s_thresh = prefix;
        __syncthreads();
    }

    const unsigned thresh = s_thresh;
    unsigned* fm = g_fmask + slice * HW4;
    const uint4* k4 = (const uint4*)keys;
    for (int j4 = tid; j4 < HW4; j4 += nt) {
        uint4 kk = __ldg(k4 + j4);
        unsigned b0 = (kk.x >= thresh) ? 1u : 0u;
        unsigned b1 = (kk.y >= thresh) ? 1u : 0u;
        unsigned b2 = (kk.z >= thresh) ? 1u : 0u;
        unsigned b3 = (kk.w >= thresh) ? 1u : 0u;
        fm[j4] = b0 | (b1 << 8) | (b2 << 16) | (b3 << 24);
    }
}

// Single fused apply over all slices: ego copy / zero store / sparse masked.
// grid (ceil(HW4/(T*UN)), C, NSLICE), UN independent float4 per thread.
__global__ void apply_kernel(const float* __restrict__ x,
                             const int* __restrict__ mask,
                             float* __restrict__ out) {
    const int slice = blockIdx.z;
    const int c = blockIdx.y;
    const int l = slice % LL;
    const size_t base = ((size_t)slice * CC + c) * (size_t)HW4;
    const float4* __restrict__ xv = (const float4*)x + base;
    float4* __restrict__ ov = (float4*)out + base;
    const int j0 = blockIdx.x * (APPLY_T * UN) + threadIdx.x;

    if (l == 0) {
        #pragma unroll
        for (int u = 0; u < UN; ++u) {
            int j = j0 + u * APPLY_T;
            if (j < HW4) __stcs(ov + j, __ldcs(xv + j));
        }
        return;
    }
    if (mask[slice] == 0) {
        const float4 z = make_float4(0.f, 0.f, 0.f, 0.f);
        #pragma unroll
        for (int u = 0; u < UN; ++u) {
            int j = j0 + u * APPLY_T;
            if (j < HW4) __stcs(ov + j, z);
        }
        return;
    }
    // masked slice: fmask word first (L1/L2-resident), x read only if needed
    const unsigned* __restrict__ fm = g_fmask + slice * HW4;
    unsigned m4[UN];
    #pragma unroll
    for (int u = 0; u < UN; ++u) {
        int j = j0 + u * APPLY_T;
        m4[u] = (j < HW4) ? __ldg(fm + j) : 0u;
    }
    float4 v[UN];
    #pragma unroll
    for (int u = 0; u < UN; ++u) {
        int j = j0 + u * APPLY_T;
        if (j < HW4 && m4[u] != 0u) v[u] = __ldcs(xv + j);
    }
    #pragma unroll
    for (int u = 0; u < UN; ++u) {
        int j = j0 + u * APPLY_T;
        if (j >= HW4) continue;
        float4 w = make_float4(0.f, 0.f, 0.f, 0.f);
        unsigned m = m4[u];
        if (m != 0u) {
            if (m & 0x000000FFu) w.x = v[u].x;
            if (m & 0x0000FF00u) w.y = v[u].y;
            if (m & 0x00FF0000u) w.z = v[u].z;
            if (m & 0xFF000000u) w.w = v[u].w;
        }
        __stcs(ov + j, w);
    }
}

extern "C" void kernel_launch(void* const* d_in, const int* in_sizes, int n_in,
                              void* d_out, int out_size) {
    const float* x = nullptr;
    const float* psm = nullptr;
    const int* mask = nullptr;
    for (int i = 0; i < n_in; ++i) {
        if (in_sizes[i] == BB * LL * CC * HW)      x    = (const float*)d_in[i];
        else if (in_sizes[i] == BB * LL * 2 * HW)  psm  = (const float*)d_in[i];
        else if (in_sizes[i] == BB * LL)           mask = (const int*)d_in[i];
    }
    float* out = (float*)d_out;

    const int kb = (NSLICE * HW4 + 255) / 256;                 // 493
    const int gx = (HW4 + APPLY_T * UN - 1) / (APPLY_T * UN);  // 7
    const dim3 agrid(gx, CC, NSLICE);

    // Fully serial: select chain is only ~11us; overlap buys nothing when
    // the apply phase is DRAM-bound (total time = bytes / BW regardless).
    compute_keys_kernel<<<kb, 256>>>(psm);
    select_finish_kernel<<<NSLICE, 1024>>>();
    apply_kernel<<<agrid, APPLY_T>>>(x, mask, out);
}

// round 15
// speedup vs baseline: 1.0960x; 1.0624x over previous
#include <cuda_runtime.h>

#define BB 4
#define LL 5
#define CC 256
#define HW 25200
#define KSEL 1024
#define NSLICE (BB*LL)
#define HW4 (HW/4)
#define UN 4          // float4s per thread in apply
#define APPLY_T 256
#define CAND_MAX 1024

// scratch (no allocations allowed)
__device__ unsigned g_keys[NSLICE * HW];      // order-preserving keys
__device__ unsigned g_fmask[NSLICE * HW4];    // 4 bytes per uint, 1 byte per hw

__device__ __forceinline__ unsigned f2ord(float f) {
    unsigned u = __float_as_uint(f);
    return u ^ ((unsigned)((int)u >> 31) | 0x80000000u);  // monotone float->uint
}

// K1 (wide, runs SOLO before the fork): keys = ord(max_c(psm_l - psm_0)).
__global__ void compute_keys_kernel(const float* __restrict__ psm) {
    int i = blockIdx.x * blockDim.x + threadIdx.x;
    if (i >= NSLICE * HW4) return;
    const int slice = i / HW4;
    const int j = i - slice * HW4;
    const int b = slice / LL;

    const float4* __restrict__ pl = (const float4*)(psm + (size_t)slice * 2 * HW);
    const float4* __restrict__ p0 = (const float4*)(psm + (size_t)(b * LL) * 2 * HW);
    float4 a0 = pl[j], a1 = pl[j + HW4];
    float4 e0 = p0[j], e1 = p0[j + HW4];
    uint4 k;
    k.x = f2ord(fmaxf(a0.x - e0.x, a1.x - e1.x));
    k.y = f2ord(fmaxf(a0.y - e0.y, a1.y - e1.y));
    k.z = f2ord(fmaxf(a0.z - e0.z, a1.z - e1.z));
    k.w = f2ord(fmaxf(a0.w - e0.w, a1.w - e1.w));
    ((uint4*)g_keys)[i] = k;
}

// K2 (20 blocks, keys L2-resident, SM/DRAM-light): histogram top-11 bits,
// shfl suffix scan, candidate gather, 21-bit syncthreads_count resolve,
// byte-mask write. Fallback radix passes if the bin is degenerate.
__global__ void select_finish_kernel() {
    __shared__ unsigned hist[2048];
    __shared__ unsigned aux[2048];
    __shared__ unsigned cand[CAND_MAX];
    __shared__ unsigned warpsum[32];
    __shared__ unsigned s_sel, s_cnt, s_thresh;
    __shared__ int s_k, s_cand_n;

    const int slice = blockIdx.x;
    const unsigned* __restrict__ keys = g_keys + (size_t)slice * HW;
    const int tid = threadIdx.x;
    const int nt = blockDim.x;        // 1024
    const int lane = tid & 31;
    const int wid = tid >> 5;

    hist[tid] = 0u; hist[tid + 1024] = 0u;
    __syncthreads();
    {
        const uint4* k4 = (const uint4*)keys;
        for (int j = tid; j < HW4; j += nt) {
            uint4 kk = __ldg(k4 + j);
            atomicAdd(&hist[kk.x >> 21], 1u);
            atomicAdd(&hist[kk.y >> 21], 1u);
            atomicAdd(&hist[kk.z >> 21], 1u);
            atomicAdd(&hist[kk.w >> 21], 1u);
        }
    }
    __syncthreads();

    // block suffix scan over 2048 bins
    {
        unsigned ps = hist[2 * tid];
        unsigned s  = ps + hist[2 * tid + 1];
        unsigned v = s;
        #pragma unroll
        for (int d = 1; d < 32; d <<= 1) {
            unsigned t = __shfl_down_sync(0xffffffffu, v, d);
            if (lane + d < 32) v += t;
        }
        if (lane == 0) warpsum[wid] = v;
        __syncthreads();
        if (wid == 0) {
            unsigned wv = warpsum[lane];
            unsigned sv = wv;
            #pragma unroll
            for (int d = 1; d < 32; d <<= 1) {
                unsigned t = __shfl_down_sync(0xffffffffu, sv, d);
                if (lane + d < 32) sv += t;
            }
            warpsum[lane] = sv - wv;
        }
        __syncthreads();
        unsigned P = v + warpsum[wid];
        aux[2 * tid]     = P;
        aux[2 * tid + 1] = P - ps;
    }
    __syncthreads();

    #pragma unroll
    for (int q = 0; q < 2; ++q) {
        int j = 2 * tid + q;
        unsigned sj  = aux[j];
        unsigned sj1 = (j < 2047) ? aux[j + 1] : 0u;
        if (sj >= KSEL && sj1 < KSEL) {
            s_sel = (unsigned)j;
            s_k   = KSEL - (int)sj1;
            s_cnt = sj - sj1;
        }
    }
    __syncthreads();

    const unsigned sel = s_sel;
    if (s_cnt <= CAND_MAX) {
        if (tid == 0) s_cand_n = 0;
        __syncthreads();
        for (int j = tid; j < HW; j += nt) {
            unsigned u = __ldg(keys + j);
            if ((u >> 21) == sel) {
                int p = atomicAdd(&s_cand_n, 1);
                cand[p] = u;
            }
        }
        __syncthreads();
        const int cn = s_cand_n;
        unsigned c = (tid < cn) ? cand[tid] : 0u;
        bool alive = (tid < cn);
        int k = s_k;
        unsigned low = 0u;
        for (int bit = 20; bit >= 0; --bit) {
            int n1 = __syncthreads_count(alive && ((c >> bit) & 1u));
            if (n1 >= k) { alive = alive && ((c >> bit) & 1u); low |= (1u << bit); }
            else         { k -= n1; alive = alive && !((c >> bit) & 1u); }
        }
        if (tid == 0) s_thresh = (sel << 21) | low;
        __syncthreads();
    } else {
        unsigned prefix = sel << 21;
        unsigned decided = 0x7FFu << 21;
        int kk = s_k;
        const int shifts[2]  = {10, 0};
        const int nbitsA[2]  = {11, 10};
        #pragma unroll
        for (int p = 0; p < 2; ++p) {
            const int shift = shifts[p];
            const int nb = 1 << nbitsA[p];
            const unsigned bm = (unsigned)nb - 1u;
            for (int j = tid; j < nb; j += nt) hist[j] = 0u;
            __syncthreads();
            for (int j = tid; j < HW; j += nt) {
                unsigned u = __ldg(keys + j);
                if ((u & decided) == prefix)
                    atomicAdd(&hist[(u >> shift) & bm], 1u);
            }
            __syncthreads();
            unsigned* src = hist;
            unsigned* dst = aux;
            for (int d = 1; d < nb; d <<= 1) {
                for (int j = tid; j < nb; j += nt)
                    dst[j] = src[j] + ((j + d < nb) ? src[j + d] : 0u);
                __syncthreads();
                unsigned* t = src; src = dst; dst = t;
            }
            for (int j = tid; j < nb; j += nt) {
                int sj  = (int)src[j];
                int sj1 = (j + 1 < nb) ? (int)src[j + 1] : 0;
                if (sj >= kk && sj1 < kk) {
                    s_sel = (unsigned)j;
                    s_cand_n = kk - sj1;
                }
            }
            __syncthreads();
            prefix |= (s_sel << shift);
            kk = s_cand_n;
            decided |= bm << shift;
            __syncthreads();
        }
        if (tid == 0) s_thresh = prefix;
        __syncthreads();
    }

    const unsigned thresh = s_thresh;
    unsigned* fm = g_fmask + slice * HW4;
    const uint4* k4 = (const uint4*)keys;
    for (int j4 = tid; j4 < HW4; j4 += nt) {
        uint4 kk = __ldg(k4 + j4);
        unsigned b0 = (kk.x >= thresh) ? 1u : 0u;
        unsigned b1 = (kk.y >= thresh) ? 1u : 0u;
        unsigned b2 = (kk.z >= thresh) ? 1u : 0u;
        unsigned b3 = (kk.w >= thresh) ? 1u : 0u;
        fm[j4] = b0 | (b1 << 8) | (b2 << 16) | (b3 << 24);
    }
}

// Easy slices: l==0 -> copy x, (l>0 && mask==0) -> zeros. No fmask dependency.
__global__ void apply_easy_kernel(const float* __restrict__ x,
                                  const int* __restrict__ mask,
                                  float* __restrict__ out) {
    const int slice = blockIdx.z;
    const int l = slice % LL;
    const bool is_ego = (l == 0);
    if (!is_ego && mask[slice] != 0) return;   // masked path handled elsewhere

    const int c = blockIdx.y;
    const size_t base = ((size_t)slice * CC + c) * (size_t)HW4;
    const float4* __restrict__ xv = (const float4*)x + base;
    float4* __restrict__ ov = (float4*)out + base;
    const int j0 = blockIdx.x * (APPLY_T * UN) + threadIdx.x;

    if (is_ego) {
        #pragma unroll
        for (int u = 0; u < UN; ++u) {
            int j = j0 + u * APPLY_T;
            if (j < HW4) __stcs(ov + j, __ldcs(xv + j));
        }
    } else {
        const float4 z = make_float4(0.f, 0.f, 0.f, 0.f);
        #pragma unroll
        for (int u = 0; u < UN; ++u) {
            int j = j0 + u * APPLY_T;
            if (j < HW4) __stcs(ov + j, z);
        }
    }
}

// Masked slices: l>0 && mask!=0 -> x * fmask, sparse x reads (fmask first,
// 16B x load only when one of its 4 lanes survives).
__global__ void apply_masked_kernel(const float* __restrict__ x,
                                    const int* __restrict__ mask,
                                    float* __restrict__ out) {
    const int slice = blockIdx.z;
    const int l = slice % LL;
    if (l == 0 || mask[slice] == 0) return;    // handled by easy kernel

    const int c = blockIdx.y;
    const size_t base = ((size_t)slice * CC + c) * (size_t)HW4;
    const float4* __restrict__ xv = (const float4*)x + base;
    float4* __restrict__ ov = (float4*)out + base;
    const int j0 = blockIdx.x * (APPLY_T * UN) + threadIdx.x;

    const unsigned* __restrict__ fm = g_fmask + slice * HW4;
    unsigned m4[UN];
    #pragma unroll
    for (int u = 0; u < UN; ++u) {
        int j = j0 + u * APPLY_T;
        m4[u] = (j < HW4) ? __ldg(fm + j) : 0u;
    }
    float4 v[UN];
    #pragma unroll
    for (int u = 0; u < UN; ++u) {
        int j = j0 + u * APPLY_T;
        if (j < HW4 && m4[u] != 0u) v[u] = __ldcs(xv + j);
    }
    #pragma unroll
    for (int u = 0; u < UN; ++u) {
        int j = j0 + u * APPLY_T;
        if (j >= HW4) continue;
        float4 w = make_float4(0.f, 0.f, 0.f, 0.f);
        unsigned m = m4[u];
        if (m != 0u) {
            if (m & 0x000000FFu) w.x = v[u].x;
            if (m & 0x0000FF00u) w.y = v[u].y;
            if (m & 0x00FF0000u) w.z = v[u].z;
            if (m & 0xFF000000u) w.w = v[u].w;
        }
        __stcs(ov + j, w);
    }
}

extern "C" void kernel_launch(void* const* d_in, const int* in_sizes, int n_in,
                              void* d_out, int out_size) {
    const float* x = nullptr;
    const float* psm = nullptr;
    const int* mask = nullptr;
    for (int i = 0; i < n_in; ++i) {
        if (in_sizes[i] == BB * LL * CC * HW)      x    = (const float*)d_in[i];
        else if (in_sizes[i] == BB * LL * 2 * HW)  psm  = (const float*)d_in[i];
        else if (in_sizes[i] == BB * LL)           mask = (const int*)d_in[i];
    }
    float* out = (float*)d_out;

    // Lazy host-side resources (no device memory involved).
    static cudaStream_t s_side = nullptr;
    static cudaEvent_t s_fork = nullptr, s_join = nullptr;
    if (!s_side) {
        cudaStreamCreateWithFlags(&s_side, cudaStreamNonBlocking);
        cudaEventCreateWithFlags(&s_fork, cudaEventDisableTiming);
        cudaEventCreateWithFlags(&s_join, cudaEventDisableTiming);
    }

    const int kb = (NSLICE * HW4 + 255) / 256;                 // 493
    const int gx = (HW4 + APPLY_T * UN - 1) / (APPLY_T * UN);  // 7
    const dim3 agrid(gx, CC, NSLICE);

    // Wide keys kernel runs SOLO first (no contention with apply kernels).
    compute_keys_kernel<<<kb, 256>>>(psm);

    // Fork AFTER keys: side = finish (light, 20 blocks, L2) -> masked apply;
    // main = easy apply (BW hog). Mirrors R5's winning overlap, shorter head.
    cudaEventRecord(s_fork, 0);
    cudaStreamWaitEvent(s_side, s_fork, 0);
    select_finish_kernel<<<NSLICE, 1024, 0, s_side>>>();
    apply_masked_kernel<<<agrid, APPLY_T, 0, s_side>>>(x, mask, out);
    cudaEventRecord(s_join, s_side);

    apply_easy_kernel<<<agrid, APPLY_T>>>(x, mask, out);

    cudaStreamWaitEvent(0, s_join, 0);
}